// round 17
// baseline (speedup 1.0000x reference)
#include <cuda_runtime.h>
#include <stdint.h>

typedef unsigned long long ull;

#define NMAX   100000
#define EMAX   1600000
#define DIN    128
#define DOUT   32
#define CAP    32        // bucket = 32 slots = 128B = one cache line
#define BM     128
#define BK     32

// ---- scratch (no allocations allowed) ----
__device__ float g_h[NMAX * DOUT];        // raw x@W, scaled in-place by k_scale
__device__ float g_dinv[NMAX];            // (deg)^{-1/2}, deg = in-edges + 1
__device__ int   g_fill[NMAX + 1];        // [0..NMAX): in-degree; [NMAX]: ovf count
__device__ int   g_srcs[NMAX * CAP];      // bucketed sources per dst (zero-init; only valid ids < n ever written)
__device__ int   g_ovf[2 * EMAX];         // overflow (src,dst) pairs

__device__ __forceinline__ ull pack_dup(float a) {
    ull r;
    asm("mov.b64 %0, {%1, %1};" : "=l"(r) : "f"(a));
    return r;
}
__device__ __forceinline__ void fma2(ull& acc, ull a, ull b) {
    asm("fma.rn.f32x2 %0, %1, %2, %0;" : "+l"(acc) : "l"(a), "l"(b));
}
__device__ __forceinline__ float2 unpack2(ull v) {
    float lo, hi;
    asm("mov.b64 {%0, %1}, %2;" : "=f"(lo), "=f"(hi) : "l"(v));
    return make_float2(lo, hi);
}

// ---------------------------------------------------------------------------
// Bucket placement. ~14 nodes expected to exceed CAP=32 (Poisson(16) tail);
// those edges spill to g_ovf and are applied by the cleanup blocks in k_agg.
// Dtype detection per block: int64 (LE, values < 2^31) => all odd 32-bit
// words zero; 256 random int32 samples all-zero ~1e-1280.
// ---------------------------------------------------------------------------
__global__ void k_place(const void* __restrict__ ei, int E) {
    __shared__ int s_is64;
    if (threadIdx.x == 0) s_is64 = 1;
    __syncthreads();
    if (((const unsigned*)ei)[2 * threadIdx.x + 1] != 0u) s_is64 = 0;
    __syncthreads();
    int is64 = s_is64;

    int e = blockIdx.x * blockDim.x + threadIdx.x;
    if (e >= E) return;
    int src, dst;
    if (is64) {
        src = (int)((const long long*)ei)[e];
        dst = (int)((const long long*)ei)[(long long)E + e];
    } else {
        src = ((const int*)ei)[e];
        dst = ((const int*)ei)[E + e];
    }
    int pos = atomicAdd(&g_fill[dst], 1);
    if (pos < CAP) {
        g_srcs[dst * CAP + pos] = src;
    } else {
        int o = atomicAdd(&g_fill[NMAX], 1);
        if (o < EMAX) { g_ovf[2 * o] = src; g_ovf[2 * o + 1] = dst; }
    }
}

// ---------------------------------------------------------------------------
// GEMM mainloop, FFMA2 paired across column pairs (R14-proven, bit-exact
// per-element chains, same registers/occupancy as scalar). Writes RAW acc.
// ---------------------------------------------------------------------------
__global__ void k_gemm(const float* __restrict__ x, const float* __restrict__ W,
                       int n) {
    __shared__ float xs[BM][BK + 1];   // 16.5 KB
    __shared__ float ws[BK][DOUT];     // 4 KB
    int t = threadIdx.x;
    int row0 = blockIdx.x * BM;
    int tx = t & 7, ty = t >> 3;

    ull acc2[4][2];
#pragma unroll
    for (int i = 0; i < 4; i++) { acc2[i][0] = 0ull; acc2[i][1] = 0ull; }

    for (int kc = 0; kc < DIN; kc += BK) {
#pragma unroll
        for (int it = 0; it < 4; it++) {
            int i = t + it * 256;
            int r = i >> 3, k4 = i & 7;
            int gr = row0 + r;
            float4 v = make_float4(0.f, 0.f, 0.f, 0.f);
            if (gr < n)
                v = __ldcs((const float4*)&x[(size_t)gr * DIN + kc + k4 * 4]);
            xs[r][k4 * 4 + 0] = v.x;
            xs[r][k4 * 4 + 1] = v.y;
            xs[r][k4 * 4 + 2] = v.z;
            xs[r][k4 * 4 + 3] = v.w;
        }
        ((float4*)ws)[t] = ((const float4*)(W + kc * DOUT))[t];
        __syncthreads();

#pragma unroll
        for (int k = 0; k < BK; k++) {
            float a0 = xs[ty * 4 + 0][k];
            float a1 = xs[ty * 4 + 1][k];
            float a2 = xs[ty * 4 + 2][k];
            float a3 = xs[ty * 4 + 3][k];
            ulonglong2 w = *(const ulonglong2*)&ws[k][tx * 4];  // {c0,c1},{c2,c3}
            ull p0 = pack_dup(a0), p1 = pack_dup(a1);
            ull p2 = pack_dup(a2), p3 = pack_dup(a3);
            fma2(acc2[0][0], p0, w.x); fma2(acc2[0][1], p0, w.y);
            fma2(acc2[1][0], p1, w.x); fma2(acc2[1][1], p1, w.y);
            fma2(acc2[2][0], p2, w.x); fma2(acc2[2][1], p2, w.y);
            fma2(acc2[3][0], p3, w.x); fma2(acc2[3][1], p3, w.y);
        }
        __syncthreads();
    }

#pragma unroll
    for (int i = 0; i < 4; i++) {
        int row = row0 + ty * 4 + i;
        if (row >= n) break;
        float2 lo = unpack2(acc2[i][0]);
        float2 hi = unpack2(acc2[i][1]);
        float4 o = make_float4(lo.x, lo.y, hi.x, hi.y);
        *(float4*)&g_h[row * DOUT + tx * 4] = o;
    }
}

// ---------------------------------------------------------------------------
// Join epilogue: dinv = rsqrt(1+deg); g_h *= dinv; out = g_h*dinv + b.
// (Initializes out for ALL nodes, so overflow-node atomics land on valid data.)
// ---------------------------------------------------------------------------
__global__ void k_scale(const float* __restrict__ b, float* __restrict__ out, int n) {
    int tid = blockIdx.x * 256 + threadIdx.x;
    int row = tid >> 3, c4 = tid & 7;
    if (row >= n) return;
    float dinv = rsqrtf(1.0f + (float)g_fill[row]);
    if (c4 == 0) g_dinv[row] = dinv;
    float4 a = *(float4*)&g_h[row * DOUT + c4 * 4];
    float4 hs = make_float4(a.x * dinv, a.y * dinv, a.z * dinv, a.w * dinv);
    *(float4*)&g_h[row * DOUT + c4 * 4] = hs;
    float4 bb = *(const float4*)&b[c4 * 4];
    float4 o;
    o.x = fmaf(hs.x, dinv, bb.x);
    o.y = fmaf(hs.y, dinv, bb.y);
    o.z = fmaf(hs.z, dinv, bb.z);
    o.w = fmaf(hs.w, dinv, bb.w);
    *(float4*)&out[row * DOUT + c4 * 4] = o;
}

// ---------------------------------------------------------------------------
// Pull-side aggregation, FULLY UNROLLED (cnt <= CAP = 32):
// - front batch: all 8 slot-index loads hit ONE 128B line (whole bucket),
//   issued in parallel with cnt, dinv, out-row read (addresses dep. only on d)
// - 6 unconditional speculative gather groups (slots 0..23): in flight before
//   cnt even returns — removes the tail's serial L2 round-trip
// - 1 warp-uniform conditional group (slots 24..31) for cnt > 24
// - speculative reads are in-bounds/valid by construction (zero-init g_srcs,
//   only valid ids ever written); accumulation predicated by cnt
// ---------------------------------------------------------------------------
__global__ void __launch_bounds__(128) k_agg(float* __restrict__ out, int n, int nb_agg) {
    if (blockIdx.x >= nb_agg) {
        int cnt = g_fill[NMAX];
        if (cnt > EMAX) cnt = EMAX;
        int tid = (blockIdx.x - nb_agg) * 128 + threadIdx.x;
        for (int o = tid; o < cnt; o += 16 * 128) {
            int src = g_ovf[2 * o], dst = g_ovf[2 * o + 1];
            float nrm = g_dinv[dst];
            for (int c = 0; c < DOUT; c++)
                atomicAdd(&out[dst * DOUT + c], g_h[src * DOUT + c] * nrm);
        }
        return;
    }

    int warp = threadIdx.x >> 5, lane = threadIdx.x & 31;
    int d = blockIdx.x * 4 + warp;
    if (d >= n) return;

    int q  = lane >> 3;
    int c4 = lane & 7;

    const int* sr = &g_srcs[d * CAP];

    // --- parallel front batch (one bucket line + scalars + out row) ---
    int s0 = sr[q];
    int s1 = sr[4 + q];
    int s2 = sr[8 + q];
    int s3 = sr[12 + q];
    int s4 = sr[16 + q];
    int s5 = sr[20 + q];
    int cnt_raw = g_fill[d];
    float dd = g_dinv[d];
    float4* op = (float4*)&out[d * DOUT + c4 * 4];
    float4 oval = *op;

    // --- 24 unconditional speculative h gathers ---
    float4 h0 = *(const float4*)&g_h[s0 * DOUT + c4 * 4];
    float4 h1 = *(const float4*)&g_h[s1 * DOUT + c4 * 4];
    float4 h2 = *(const float4*)&g_h[s2 * DOUT + c4 * 4];
    float4 h3 = *(const float4*)&g_h[s3 * DOUT + c4 * 4];
    float4 h4 = *(const float4*)&g_h[s4 * DOUT + c4 * 4];
    float4 h5 = *(const float4*)&g_h[s5 * DOUT + c4 * 4];

    int cnt = cnt_raw > CAP ? CAP : cnt_raw;

    float4 a0 = make_float4(0.f, 0.f, 0.f, 0.f);
    float4 a1 = make_float4(0.f, 0.f, 0.f, 0.f);
    if (q      < cnt) { a0.x += h0.x; a0.y += h0.y; a0.z += h0.z; a0.w += h0.w; }
    if (4 + q  < cnt) { a1.x += h1.x; a1.y += h1.y; a1.z += h1.z; a1.w += h1.w; }
    if (8 + q  < cnt) { a0.x += h2.x; a0.y += h2.y; a0.z += h2.z; a0.w += h2.w; }
    if (12 + q < cnt) { a1.x += h3.x; a1.y += h3.y; a1.z += h3.z; a1.w += h3.w; }
    if (16 + q < cnt) { a0.x += h4.x; a0.y += h4.y; a0.z += h4.z; a0.w += h4.w; }
    if (20 + q < cnt) { a1.x += h5.x; a1.y += h5.y; a1.z += h5.z; a1.w += h5.w; }

    // --- conditional last group (warp-uniform branch; src loads are L1 hits) ---
    if (cnt > 24) {
        int t0 = sr[24 + q];
        int t1 = sr[28 + q];
        float4 g0 = *(const float4*)&g_h[t0 * DOUT + c4 * 4];
        float4 g1 = *(const float4*)&g_h[t1 * DOUT + c4 * 4];
        if (24 + q < cnt) { a0.x += g0.x; a0.y += g0.y; a0.z += g0.z; a0.w += g0.w; }
        if (28 + q < cnt) { a1.x += g1.x; a1.y += g1.y; a1.z += g1.z; a1.w += g1.w; }
    }

    a0.x += a1.x; a0.y += a1.y; a0.z += a1.z; a0.w += a1.w;

    // reduce quarters (lane bits 3,4)
    a0.x += __shfl_xor_sync(0xffffffffu, a0.x, 8);
    a0.y += __shfl_xor_sync(0xffffffffu, a0.y, 8);
    a0.z += __shfl_xor_sync(0xffffffffu, a0.z, 8);
    a0.w += __shfl_xor_sync(0xffffffffu, a0.w, 8);
    a0.x += __shfl_xor_sync(0xffffffffu, a0.x, 16);
    a0.y += __shfl_xor_sync(0xffffffffu, a0.y, 16);
    a0.z += __shfl_xor_sync(0xffffffffu, a0.z, 16);
    a0.w += __shfl_xor_sync(0xffffffffu, a0.w, 16);

    if (lane < 8) {
        if (cnt_raw <= CAP) {
            oval.x = fmaf(a0.x, dd, oval.x);
            oval.y = fmaf(a0.y, dd, oval.y);
            oval.z = fmaf(a0.z, dd, oval.z);
            oval.w = fmaf(a0.w, dd, oval.w);
            *op = oval;
        } else {
            // overflow node (~1e-4 of nodes): cleanup blocks also write -> atomic
            float* os = (float*)op;
            atomicAdd(os + 0, a0.x * dd);
            atomicAdd(os + 1, a0.y * dd);
            atomicAdd(os + 2, a0.z * dd);
            atomicAdd(os + 3, a0.w * dd);
        }
    }
}

// ---------------------------------------------------------------------------
// Launch graph:
//   s0: memset(fill) -> k_place ─┐
//   s2: k_gemm (independent)    ─┴─ join -> k_scale -> k_agg
// Stream/events created lazily on the FIRST (uncaptured) call only.
// ---------------------------------------------------------------------------
extern "C" void kernel_launch(void* const* d_in, const int* in_sizes, int n_in,
                              void* d_out, int out_size) {
    const float* x  = (const float*)d_in[0];
    const void*  ei = d_in[1];
    const float* W  = (const float*)d_in[2];
    const float* b  = (const float*)d_in[3];
    float* out = (float*)d_out;

    int n = in_sizes[0] / DIN;   // 100000
    int E = in_sizes[1] / 2;     // 1600000

    static cudaStream_t s2 = nullptr;
    static cudaEvent_t evFork = nullptr, evJoin = nullptr;
    if (!s2) {
        cudaStreamCreateWithFlags(&s2, cudaStreamNonBlocking);
        cudaEventCreateWithFlags(&evFork, cudaEventDisableTiming);
        cudaEventCreateWithFlags(&evJoin, cudaEventDisableTiming);
    }

    void* fill_ptr = nullptr;
    cudaGetSymbolAddress(&fill_ptr, g_fill);

    // fork: gemm branch on s2 (touches only x, W, g_h)
    cudaEventRecord(evFork, 0);
    cudaStreamWaitEvent(s2, evFork, 0);
    k_gemm<<<(n + BM - 1) / BM, 256, 0, s2>>>(x, W, n);
    cudaEventRecord(evJoin, s2);

    // place branch on stream 0
    cudaMemsetAsync(fill_ptr, 0, (NMAX + 1) * sizeof(int), 0);
    k_place<<<(E + 255) / 256, 256>>>(ei, E);

    // join, then epilogue + aggregation
    cudaStreamWaitEvent(0, evJoin, 0);
    k_scale<<<(n * 8 + 255) / 256, 256>>>(b, out, n);

    int nb_agg = (n + 3) / 4;
    k_agg<<<nb_agg + 16, 128>>>(out, n, nb_agg);
}